// round 2
// baseline (speedup 1.0000x reference)
#include <cuda_runtime.h>
#include <cstdint>

#define N_NODES 1024
#define F_IN    32
#define HID     64
#define OUTF    32

// Scratch (device globals are the allowed scratch mechanism)
__device__ float g_A[N_NODES * HID];
__device__ float g_B[N_NODES * HID];

// ---------------------------------------------------------------------------
// Prep: A[i][h] = sum_f Emb[i][f]*W1[h][f]; B[i][h] = sum_f Emb[i][f]*W1[h][F+f]
// ---------------------------------------------------------------------------
__global__ void prep_kernel(const float* __restrict__ Emb,
                            const float* __restrict__ W1) {
    __shared__ float sW1[HID * 65];
    __shared__ float sE[F_IN];
    const int i = blockIdx.x;
    const int h = threadIdx.x;

    for (int idx = h; idx < HID * 2 * F_IN; idx += 64) {
        int r = idx >> 6, c = idx & 63;
        sW1[r * 65 + c] = W1[idx];
    }
    if (h < F_IN) sE[h] = Emb[i * F_IN + h];
    __syncthreads();

    float a = 0.f, b = 0.f;
#pragma unroll
    for (int f = 0; f < F_IN; f++) {
        float e = sE[f];
        a = fmaf(e, sW1[h * 65 + f], a);
        b = fmaf(e, sW1[h * 65 + F_IN + f], b);
    }
    g_A[i * HID + h] = a;
    g_B[i * HID + h] = b;
}

// swish via 2 MUFU (EX2 + RCP through div.approx) — rel err ~1e-6, cheap.
__device__ __forceinline__ float swishf(float x) {
    return __fdividef(x, 1.0f + __expf(-x));
}

// Pack two floats into a b64 register pair (free in SASS: register pairing).
__device__ __forceinline__ unsigned long long pack2(float lo, float hi) {
    unsigned long long r;
    asm("mov.b64 %0, {%1,%2};" : "=l"(r) : "f"(lo), "f"(hi));
    return r;
}
__device__ __forceinline__ void unpack2(unsigned long long v, float& lo, float& hi) {
    asm("mov.b64 {%0,%1}, %2;" : "=f"(lo), "=f"(hi) : "l"(v));
}
__device__ __forceinline__ void fma2(unsigned long long& acc,
                                     unsigned long long a,
                                     unsigned long long b) {
    asm("fma.rn.f32x2 %0, %1, %2, %0;" : "+l"(acc) : "l"(a), "l"(b));
}
__device__ __forceinline__ void add2(unsigned long long& acc,
                                     unsigned long long b) {
    asm("add.rn.f32x2 %0, %0, %1;" : "+l"(acc) : "l"(b));
}

// ---------------------------------------------------------------------------
// Main: grid (N/32, N/8), block 256 = 8 warps. Warp w owns row i = i0+w,
// iterates the 32 j's of the block's column tile. Per pair:
//   phase A: lanes produce h1[0..63] (2 swishes/lane) into per-warp smem buf
//   phase B: lane = output channel o; 64-dot via float4 broadcast loads of sH
//            + packed fma.rn.f32x2 with W2 row held in 32 b64 registers.
// ---------------------------------------------------------------------------
__global__ __launch_bounds__(256) void phi_e_kernel(
    const float* __restrict__ Edges,
    const float* __restrict__ Coords,
    const float* __restrict__ b1,
    const float* __restrict__ W2,
    const float* __restrict__ b2,
    float* __restrict__ out)
{
    __shared__ float sB[32 * HID];                    // B rows for the j-tile
    __shared__ float sW[256];                         // w_ij = Edges*dist
    __shared__ __align__(16) float sH[8][HID];        // per-warp h1 buffer

    const int tid  = threadIdx.x;
    const int warp = tid >> 5;
    const int lane = tid & 31;
    const int i0 = blockIdx.y * 8;
    const int j0 = blockIdx.x * 32;

    // Stage B tile: contiguous 2048 floats, fully coalesced.
    {
        const float* gB = g_B + j0 * HID;
        for (int k = tid; k < 32 * HID; k += 256) sB[k] = gB[k];
    }

    // Pair weights: thread t -> pair (ii = t>>5, jj = t&31).
    {
        const int ii = i0 + (tid >> 5);
        const int jj = j0 + (tid & 31);
        float e  = Edges[ii * N_NODES + jj];
        float dx = Coords[ii * 3 + 0] - Coords[jj * 3 + 0];
        float dy = Coords[ii * 3 + 1] - Coords[jj * 3 + 1];
        float dz = Coords[ii * 3 + 2] - Coords[jj * 3 + 2];
        float sq = fmaf(dx, dx, fmaf(dy, dy, dz * dz));
        float dist = sq > 0.f ? __fsqrt_rn(sq) : 0.f;
        sW[tid] = e * dist;
    }

    // Per-lane constants.
    const int i = i0 + warp;
    const float aLo  = g_A[i * HID + lane];
    const float aHi  = g_A[i * HID + 32 + lane];
    const float b1Lo = b1[lane];
    const float b1Hi = b1[lane + 32];
    const float b2v  = b2[lane];

    // W2 row for o = lane as 32 packed f32x2 registers (C++ float4 loads).
    unsigned long long w2r[32];
    {
        const float* wrow = W2 + lane * HID;
#pragma unroll
        for (int m = 0; m < 16; m++) {
            float4 v = __ldg((const float4*)(wrow + 4 * m));
            w2r[2 * m]     = pack2(v.x, v.y);
            w2r[2 * m + 1] = pack2(v.z, v.w);
        }
    }
    __syncthreads();

    float* orow = out + ((size_t)i * N_NODES + j0) * OUTF;
    const float* myH = &sH[warp][0];

    for (int j = 0; j < 32; j++) {
        // ---- phase A: h1 for this pair (lanes cover h and h+32) ----
        float wv = sW[warp * 32 + j];
        float bl = sB[j * HID + lane];
        float bh = sB[j * HID + 32 + lane];
        float p0 = fmaf(wv, aLo + bl, b1Lo);
        float p1 = fmaf(wv, aHi + bh, b1Hi);
        sH[warp][lane]      = swishf(p0);
        sH[warp][lane + 32] = swishf(p1);
        __syncwarp();

        // ---- phase B: out[o=lane] = swish(dot64(h1, W2row) + b2) ----
        unsigned long long acc0 = pack2(0.f, 0.f);
        unsigned long long acc1 = acc0, acc2 = acc0, acc3 = acc0;
#pragma unroll
        for (int m = 0; m < 16; m += 2) {
            float4 ha = *(const float4*)(myH + 4 * m);        // LDS.128 broadcast
            float4 hb = *(const float4*)(myH + 4 * m + 4);
            fma2(acc0, pack2(ha.x, ha.y), w2r[2 * m]);
            fma2(acc1, pack2(ha.z, ha.w), w2r[2 * m + 1]);
            fma2(acc2, pack2(hb.x, hb.y), w2r[2 * m + 2]);
            fma2(acc3, pack2(hb.z, hb.w), w2r[2 * m + 3]);
        }
        __syncwarp();   // protect sH before next iteration's writes

        add2(acc0, acc1);
        add2(acc2, acc3);
        add2(acc0, acc2);
        float lo, hi;
        unpack2(acc0, lo, hi);
        float pre2 = (lo + hi) + b2v;
        orow[j * OUTF + lane] = swishf(pre2);
    }
}

// ---------------------------------------------------------------------------
extern "C" void kernel_launch(void* const* d_in, const int* in_sizes, int n_in,
                              void* d_out, int out_size) {
    const float* Edges  = (const float*)d_in[0];
    const float* Coords = (const float*)d_in[1];
    const float* Emb    = (const float*)d_in[2];
    const float* W1     = (const float*)d_in[3];
    const float* b1     = (const float*)d_in[4];
    const float* W2     = (const float*)d_in[5];
    const float* b2     = (const float*)d_in[6];
    float* out = (float*)d_out;

    prep_kernel<<<N_NODES, 64>>>(Emb, W1);

    dim3 grid(N_NODES / 32, N_NODES / 8);
    phi_e_kernel<<<grid, 256>>>(Edges, Coords, b1, W2, b2, out);
}

// round 4
// speedup vs baseline: 1.9298x; 1.9298x over previous
#include <cuda_runtime.h>
#include <cstdint>

#define N_NODES 1024
#define F_IN    32
#define HID     64
#define OUTF    32

typedef unsigned long long u64;

// Scratch
__device__ float  g_A [N_NODES * HID];            // A[i][h]
__device__ float2 g_Bt[(HID / 2) * N_NODES];      // Bt[hp][i] = (B[i][2hp], B[i][2hp+1])

// ---------------------------------------------------------------------------
// Prep: A[i][h] = Emb[i]·W1[h][:F];  B[i][h] = Emb[i]·W1[h][F:]
// ---------------------------------------------------------------------------
__global__ void prep_kernel(const float* __restrict__ Emb,
                            const float* __restrict__ W1) {
    __shared__ float sW1[HID * 65];
    __shared__ float sE[F_IN];
    const int i = blockIdx.x;
    const int h = threadIdx.x;

    for (int idx = h; idx < HID * 2 * F_IN; idx += 64) {
        int r = idx >> 6, c = idx & 63;
        sW1[r * 65 + c] = W1[idx];
    }
    if (h < F_IN) sE[h] = Emb[i * F_IN + h];
    __syncthreads();

    float a = 0.f, b = 0.f;
#pragma unroll
    for (int f = 0; f < F_IN; f++) {
        float e = sE[f];
        a = fmaf(e, sW1[h * 65 + f], a);
        b = fmaf(e, sW1[h * 65 + F_IN + f], b);
    }
    g_A[i * HID + h] = a;
    ((float*)g_Bt)[(h >> 1) * (2 * N_NODES) + i * 2 + (h & 1)] = b;
}

__device__ __forceinline__ float swishf(float x) {
    return __fdividef(x, 1.0f + __expf(-x));
}
__device__ __forceinline__ u64 pack2(float lo, float hi) {
    u64 r; asm("mov.b64 %0, {%1,%2};" : "=l"(r) : "f"(lo), "f"(hi)); return r;
}
__device__ __forceinline__ void unpack2(u64 v, float& lo, float& hi) {
    asm("mov.b64 {%0,%1}, %2;" : "=f"(lo), "=f"(hi) : "l"(v));
}
__device__ __forceinline__ void fma2(u64& acc, u64 a, u64 b) {
    asm("fma.rn.f32x2 %0, %1, %2, %0;" : "+l"(acc) : "l"(a), "l"(b));
}

// ---------------------------------------------------------------------------
// Main: grid (N/64, N/8), block 256 = 8 warps. Warp w owns row i = i0+w.
// Lane owns TWO pairs: (i, j0+lane) and (i, j0+32+lane); all 32 outputs per
// pair live in 16 packed f32x2 registers. h1 is computed and consumed entirely
// in registers (no per-pair shared traffic). W2^T rows broadcast from smem.
// ---------------------------------------------------------------------------
__global__ __launch_bounds__(256) void phi_e_kernel(
    const float* __restrict__ Edges,
    const float* __restrict__ Coords,
    const float* __restrict__ b1,
    const float* __restrict__ W2,
    const float* __restrict__ b2,
    float* __restrict__ out)
{
    __shared__ float2 sB2[HID / 2][64];                    // Bt tile for 64 j's
    __shared__ __align__(16) float sW2T[HID * 36];         // W2^T, rows padded to 36
    __shared__ float4 sC[8][HID / 2];                      // (A[2hp], b1[2hp], A[2hp+1], b1[2hp+1])
    __shared__ float  sb2s[OUTF];
    __shared__ float  sOut[8][32][17];                     // output staging

    const int tid  = threadIdx.x;
    const int warp = tid >> 5;
    const int lane = tid & 31;
    const int i0 = blockIdx.y * 8;
    const int j0 = blockIdx.x * 64;
    const int i  = i0 + warp;

    for (int e = tid; e < (HID / 2) * 64; e += 256) {
        int hp = e >> 6, jj = e & 63;
        sB2[hp][jj] = g_Bt[hp * N_NODES + j0 + jj];
    }
    for (int idx = tid; idx < OUTF * HID; idx += 256) {
        int o = idx >> 6, h = idx & 63;
        sW2T[h * 36 + o] = W2[idx];
    }
    {
        float2 a2 = ((const float2*)g_A)[i * (HID / 2) + lane];
        float2 bb = ((const float2*)b1)[lane];
        sC[warp][lane] = make_float4(a2.x, bb.x, a2.y, bb.y);
    }
    if (tid < OUTF) sb2s[tid] = b2[tid];

    float wA, wB;
    {
        float cx = Coords[i * 3 + 0], cy = Coords[i * 3 + 1], cz = Coords[i * 3 + 2];
        int jA = j0 + lane, jB = j0 + 32 + lane;
        float dxA = cx - Coords[jA * 3 + 0], dyA = cy - Coords[jA * 3 + 1], dzA = cz - Coords[jA * 3 + 2];
        float dxB = cx - Coords[jB * 3 + 0], dyB = cy - Coords[jB * 3 + 1], dzB = cz - Coords[jB * 3 + 2];
        float sqA = fmaf(dxA, dxA, fmaf(dyA, dyA, dzA * dzA));
        float sqB = fmaf(dxB, dxB, fmaf(dyB, dyB, dzB * dzB));
        float dA = sqA > 0.f ? __fsqrt_rn(sqA) : 0.f;
        float dB = sqB > 0.f ? __fsqrt_rn(sqB) : 0.f;
        wA = Edges[i * N_NODES + jA] * dA;
        wB = Edges[i * N_NODES + jB] * dB;
    }
    __syncthreads();

    u64 accA[16], accB[16];
    const u64 z = pack2(0.f, 0.f);
#pragma unroll
    for (int p = 0; p < 16; p++) { accA[p] = z; accB[p] = z; }

#pragma unroll 4
    for (int hp = 0; hp < HID / 2; hp++) {
        float4 c  = sC[warp][hp];                  // broadcast LDS.128
        float2 bA = sB2[hp][lane];                 // conflict-free LDS.64
        float2 bB = sB2[hp][32 + lane];

        float hA0 = swishf(fmaf(wA, c.x + bA.x, c.y));
        float hA1 = swishf(fmaf(wA, c.z + bA.y, c.w));
        float hB0 = swishf(fmaf(wB, c.x + bB.x, c.y));
        float hB1 = swishf(fmaf(wB, c.z + bB.y, c.w));
        u64 pA0 = pack2(hA0, hA0), pA1 = pack2(hA1, hA1);
        u64 pB0 = pack2(hB0, hB0), pB1 = pack2(hB1, hB1);

        const ulonglong2* r0 = (const ulonglong2*)(sW2T + (2 * hp)     * 36);
        const ulonglong2* r1 = (const ulonglong2*)(sW2T + (2 * hp + 1) * 36);
#pragma unroll
        for (int q = 0; q < 8; q++) {
            ulonglong2 w0 = r0[q];                 // broadcast LDS.128
            ulonglong2 w1 = r1[q];
            fma2(accA[2 * q],     pA0, w0.x);
            fma2(accA[2 * q + 1], pA0, w0.y);
            fma2(accA[2 * q],     pA1, w1.x);
            fma2(accA[2 * q + 1], pA1, w1.y);
            fma2(accB[2 * q],     pB0, w0.x);
            fma2(accB[2 * q + 1], pB0, w0.y);
            fma2(accB[2 * q],     pB1, w1.x);
            fma2(accB[2 * q + 1], pB1, w1.y);
        }
    }

    // ---- epilogue: +b2, swish, coalesced store via padded smem transpose ----
    const int t   = lane & 15;
    const int jj2 = lane >> 4;
#pragma unroll
    for (int s = 0; s < 2; s++) {
        u64* acc = s ? accB : accA;
        float* obase = out + ((size_t)i * N_NODES + j0 + (s ? 32 : 0)) * OUTF;

        float vals[32];
#pragma unroll
        for (int p = 0; p < 16; p++) unpack2(acc[p], vals[2 * p], vals[2 * p + 1]);
#pragma unroll
        for (int o = 0; o < OUTF; o++) vals[o] = swishf(vals[o] + sb2s[o]);

#pragma unroll
        for (int r = 0; r < 2; r++) {
#pragma unroll
            for (int k = 0; k < 16; k++) sOut[warp][lane][k] = vals[16 * r + k];
            __syncwarp();
#pragma unroll
            for (int c = 0; c < 16; c++) {
                int jj = 2 * c + jj2;
                obase[jj * OUTF + 16 * r + t] = sOut[warp][jj][t];
            }
            __syncwarp();
        }
    }
}

// ---------------------------------------------------------------------------
extern "C" void kernel_launch(void* const* d_in, const int* in_sizes, int n_in,
                              void* d_out, int out_size) {
    const float* Edges  = (const float*)d_in[0];
    const float* Coords = (const float*)d_in[1];
    const float* Emb    = (const float*)d_in[2];
    const float* W1     = (const float*)d_in[3];
    const float* b1     = (const float*)d_in[4];
    const float* W2     = (const float*)d_in[5];
    const float* b2     = (const float*)d_in[6];
    float* out = (float*)d_out;

    prep_kernel<<<N_NODES, 64>>>(Emb, W1);

    dim3 grid(N_NODES / 64, N_NODES / 8);
    phi_e_kernel<<<grid, 256>>>(Edges, Coords, b1, W2, b2, out);
}